// round 1
// baseline (speedup 1.0000x reference)
#include <cuda_runtime.h>

#define BATCH 4
#define C3 256
#define HH 48
#define WW 48
#define L 2304      // HH*WW positions
#define DD 2304     // C3*9 patch dim

// ---------------- device scratch (no allocs allowed) ----------------
__device__ float g_A[(size_t)BATCH * L * DD];   // rs_n, row-major [l][d], 85MB
__device__ float g_Bm[(size_t)BATCH * DD * L];  // lr_n, row-major [d][m], 85MB
__device__ float g_Prs[BATCH * L];
__device__ float g_Plr[BATCH * L];
__device__ float g_invA[BATCH * L];
__device__ float g_invB[BATCH * L];
__device__ unsigned long long g_best[BATCH * L];
__device__ int g_arg[BATCH * L];

// monotonic float<->uint key (total order matching float compare)
__device__ __forceinline__ unsigned fkey(float f) {
    unsigned u = __float_as_uint(f);
    return (u & 0x80000000u) ? ~u : (u | 0x80000000u);
}
__device__ __forceinline__ float fkeyinv(unsigned k) {
    unsigned u = (k & 0x80000000u) ? (k & 0x7FFFFFFFu) : ~k;
    return __uint_as_float(u);
}

// ---------------- 1. per-pixel channel squared sums ----------------
// grid: BATCH*HH blocks, 64 threads (48 active); coalesced 48-wide rows
__global__ void k_sqsum(const float* __restrict__ lrsr, const float* __restrict__ refsr) {
    int b = blockIdx.x / HH;
    int y = blockIdx.x % HH;
    int x = threadIdx.x;
    if (x >= WW) return;
    size_t base = ((size_t)b * C3 * HH + y) * WW + x;
    float srs = 0.f, slr = 0.f;
    for (int c = 0; c < C3; c++) {
        float v = refsr[base + (size_t)c * HH * WW];
        srs = fmaf(v, v, srs);
        v = lrsr[base + (size_t)c * HH * WW];
        slr = fmaf(v, v, slr);
    }
    g_Prs[b * L + y * WW + x] = srs;
    g_Plr[b * L + y * WW + x] = slr;
}

// ---------------- 2. 3x3 window norms + best-init ----------------
__global__ void k_norms() {
    int i = blockIdx.x * blockDim.x + threadIdx.x;
    if (i >= BATCH * L) return;
    int b = i / L, p = i % L, y = p / WW, x = p % WW;
    float wr = 0.f, wl = 0.f;
    #pragma unroll
    for (int dy = -1; dy <= 1; dy++) {
        int yy = y + dy;
        if ((unsigned)yy >= HH) continue;
        #pragma unroll
        for (int dx = -1; dx <= 1; dx++) {
            int xx = x + dx;
            if ((unsigned)xx >= WW) continue;
            wr += g_Prs[b * L + yy * WW + xx];
            wl += g_Plr[b * L + yy * WW + xx];
        }
    }
    g_invA[i] = 1.f / fmaxf(sqrtf(wr), 1e-12f);
    g_invB[i] = 1.f / fmaxf(sqrtf(wl), 1e-12f);
    g_best[i] = 0ull;  // key 0 < any real float key
}

// ---------------- 3. build A = rs_n  [l][d] ----------------
// block per (b,l): coalesced writes along d
__global__ void k_buildA(const float* __restrict__ refsr) {
    int b = blockIdx.x / L, l = blockIdx.x % L;
    int ly = l / WW, lx = l % WW;
    float inv = g_invA[b * L + l];
    float* dst = g_A + ((size_t)b * L + l) * DD;
    const float* src = refsr + (size_t)b * C3 * HH * WW;
    for (int d = threadIdx.x; d < DD; d += blockDim.x) {
        int c = d / 9, kk = d % 9, ki = kk / 3, kj = kk % 3;
        int yy = ly + ki - 1, xx = lx + kj - 1;
        float v = 0.f;
        if ((unsigned)yy < HH && (unsigned)xx < WW)
            v = src[((size_t)c * HH + yy) * WW + xx];
        dst[d] = v * inv;
    }
}

// ---------------- 4. build B = lr_n  [d][m] ----------------
// block per (b,d): coalesced writes and (mostly) coalesced reads along m
__global__ void k_buildB(const float* __restrict__ lrsr) {
    int b = blockIdx.x / DD, d = blockIdx.x % DD;
    int c = d / 9, kk = d % 9, ki = kk / 3, kj = kk % 3;
    float* dst = g_Bm + ((size_t)b * DD + d) * L;
    const float* src = lrsr + ((size_t)b * C3 + c) * HH * WW;
    const float* invB = g_invB + b * L;
    for (int m = threadIdx.x; m < L; m += blockDim.x) {
        int my = m / WW, mx = m % WW;
        int yy = my + ki - 1, xx = mx + kj - 1;
        float v = 0.f;
        if ((unsigned)yy < HH && (unsigned)xx < WW)
            v = src[yy * WW + xx];
        dst[m] = v * invB[m];
    }
}

// ---------------- 5. SGEMM 128x128x8 + fused column argmax ----------------
// grid (18, 18, BATCH), 256 threads, 8x8 per-thread tile
__global__ void __launch_bounds__(256) k_gemm_argmax() {
    int b = blockIdx.z;
    int mbase = blockIdx.x * 128;
    int lbase = blockIdx.y * 128;
    const float* A = g_A + (size_t)b * L * DD;
    const float* Bm = g_Bm + (size_t)b * DD * L;

    __shared__ float As[8][128];
    __shared__ float Bs[8][128];
    __shared__ unsigned long long red[16][128];

    int t = threadIdx.x;
    int tx = t & 15, ty = t >> 4;

    float acc[8][8];
    #pragma unroll
    for (int i = 0; i < 8; i++)
        #pragma unroll
        for (int j = 0; j < 8; j++) acc[i][j] = 0.f;

    int la = t >> 1;              // A row within tile
    int ka = (t & 1) << 2;        // A k-offset (0 or 4)
    int kb = t >> 5;              // B k row
    int mb = (t & 31) << 2;       // B col offset
    const float* aptr = A + (size_t)(lbase + la) * DD + ka;
    const float* bptr = Bm + (size_t)kb * L + mbase + mb;

    for (int k0 = 0; k0 < DD; k0 += 8) {
        float4 av = *(const float4*)(aptr + k0);
        float4 bv = *(const float4*)(bptr + (size_t)k0 * L);
        __syncthreads();
        As[ka + 0][la] = av.x;
        As[ka + 1][la] = av.y;
        As[ka + 2][la] = av.z;
        As[ka + 3][la] = av.w;
        *(float4*)&Bs[kb][mb] = bv;
        __syncthreads();
        #pragma unroll
        for (int k = 0; k < 8; k++) {
            float a[8], bb[8];
            #pragma unroll
            for (int i = 0; i < 8; i++) a[i] = As[k][ty * 8 + i];
            #pragma unroll
            for (int j = 0; j < 8; j++) bb[j] = Bs[k][tx * 8 + j];
            #pragma unroll
            for (int i = 0; i < 8; i++)
                #pragma unroll
                for (int j = 0; j < 8; j++)
                    acc[i][j] = fmaf(a[i], bb[j], acc[i][j]);
        }
    }

    // per-thread max over its 8 rows, per column; pack (key, ~l) so ties pick lowest l
    #pragma unroll
    for (int j = 0; j < 8; j++) {
        float best = acc[0][j];
        int bi = 0;
        #pragma unroll
        for (int i = 1; i < 8; i++)
            if (acc[i][j] > best) { best = acc[i][j]; bi = i; }
        unsigned lidx = (unsigned)(lbase + ty * 8 + bi);
        red[ty][tx * 8 + j] =
            ((unsigned long long)fkey(best) << 32) | (unsigned long long)(0xFFFFFFFFu - lidx);
    }
    __syncthreads();
    if (t < 128) {
        unsigned long long m = red[0][t];
        #pragma unroll
        for (int r = 1; r < 16; r++) {
            unsigned long long v = red[r][t];
            if (v > m) m = v;
        }
        atomicMax(&g_best[b * L + mbase + t], m);
    }
}

// ---------------- 6. decode best -> S output + arg indices ----------------
__global__ void k_decode(float* __restrict__ outS) {
    int i = blockIdx.x * blockDim.x + threadIdx.x;
    if (i >= BATCH * L) return;
    unsigned long long p = g_best[i];
    outS[i] = fkeyinv((unsigned)(p >> 32));
    g_arg[i] = (int)(0xFFFFFFFFu - (unsigned)(p & 0xFFFFFFFFu));
}

// ---------------- 7. gather + fold (closed form: 9 contributions/pixel) ----------------
// out[b,c,y,x] = (1/9) * sum over oh in {qy-1,qy,qy+1}, ow in {qx-1,qx,qx+1}
//   of ref[b,c, s*ry(arg)+ki-s, s*rx(arg)+kj-s]   (OOB -> 0)
__global__ void k_gather(const float* __restrict__ ref, float* __restrict__ out,
                         int C, int s, int Hs) {
    int b = blockIdx.z, c = blockIdx.y;
    int p = blockIdx.x * blockDim.x + threadIdx.x;
    int y = p / Hs, x = p % Hs;
    int qy = y / s, ry = y % s, qx = x / s, rxr = x % s;
    const int* argb = g_arg + b * L;
    const float* refc = ref + ((size_t)b * C + c) * Hs * Hs;
    float sum = 0.f;
    #pragma unroll
    for (int dy = 0; dy < 3; dy++) {
        int oh = qy + 1 - dy;
        if ((unsigned)oh >= HH) continue;
        int ki = ry + s * dy;
        #pragma unroll
        for (int dx = 0; dx < 3; dx++) {
            int ow = qx + 1 - dx;
            if ((unsigned)ow >= WW) continue;
            int kj = rxr + s * dx;
            int j = __ldg(argb + oh * WW + ow);
            int sy = s * (j / WW) + ki - s;
            int sx = s * (j % WW) + kj - s;
            if ((unsigned)sy < (unsigned)Hs && (unsigned)sx < (unsigned)Hs)
                sum += __ldg(refc + sy * Hs + sx);
        }
    }
    out[((size_t)b * C + c) * (size_t)(Hs * Hs) + p] = sum * (1.f / 9.f);
}

// ---------------- launch ----------------
extern "C" void kernel_launch(void* const* d_in, const int* in_sizes, int n_in,
                              void* d_out, int out_size) {
    const float* lrsr = (const float*)d_in[0];
    const float* refsr = (const float*)d_in[1];
    const float* ref1 = (const float*)d_in[2];
    const float* ref2 = (const float*)d_in[3];
    const float* ref3 = (const float*)d_in[4];
    float* out = (float*)d_out;

    float* outS = out;                            // (4,1,48,48)
    float* outT3 = outS + BATCH * L;              // (4,256,48,48)
    float* outT2 = outT3 + BATCH * C3 * HH * WW;  // (4,128,96,96)
    float* outT1 = outT2 + BATCH * 128 * 96 * 96; // (4,64,192,192)

    k_sqsum<<<BATCH * HH, 64>>>(lrsr, refsr);
    k_norms<<<(BATCH * L + 255) / 256, 256>>>();
    k_buildA<<<BATCH * L, 256>>>(refsr);
    k_buildB<<<BATCH * DD, 256>>>(lrsr);
    dim3 g(18, 18, BATCH);
    k_gemm_argmax<<<g, 256>>>();
    k_decode<<<(BATCH * L + 255) / 256, 256>>>(outS);
    k_gather<<<dim3(2304 / 256, C3, BATCH), 256>>>(ref3, outT3, C3, 1, 48);
    k_gather<<<dim3(9216 / 256, 128, BATCH), 256>>>(ref2, outT2, 128, 2, 96);
    k_gather<<<dim3(36864 / 256, 64, BATCH), 256>>>(ref1, outT1, 64, 4, 192);
}

// round 2
// speedup vs baseline: 4.5493x; 4.5493x over previous
#include <cuda_runtime.h>

#define BATCH 4
#define C3 256
#define HH 48
#define WW 48
#define L 2304      // HH*WW positions
#define LP1 2305    // L+1, diagonal shift stride

// ---------------- device scratch (no allocs allowed) ----------------
__device__ float g_G[(size_t)BATCH * L * L];   // pixel Gram matrix, 85MB
__device__ float g_Prs[BATCH * L];
__device__ float g_Plr[BATCH * L];
__device__ float g_invA[BATCH * L];
__device__ float g_invB[BATCH * L];
__device__ unsigned long long g_best[BATCH * L];
__device__ int g_arg[BATCH * L];

// monotonic float<->uint key (total order matching float compare)
__device__ __forceinline__ unsigned fkey(float f) {
    unsigned u = __float_as_uint(f);
    return (u & 0x80000000u) ? ~u : (u | 0x80000000u);
}
__device__ __forceinline__ float fkeyinv(unsigned k) {
    unsigned u = (k & 0x80000000u) ? (k & 0x7FFFFFFFu) : ~k;
    return __uint_as_float(u);
}

// ---------------- 1. per-pixel channel squared sums ----------------
__global__ void k_sqsum(const float* __restrict__ lrsr, const float* __restrict__ refsr) {
    int b = blockIdx.x / HH;
    int y = blockIdx.x % HH;
    int x = threadIdx.x;
    if (x >= WW) return;
    size_t base = ((size_t)b * C3 * HH + y) * WW + x;
    float srs = 0.f, slr = 0.f;
    for (int c = 0; c < C3; c++) {
        float v = refsr[base + (size_t)c * HH * WW];
        srs = fmaf(v, v, srs);
        v = lrsr[base + (size_t)c * HH * WW];
        slr = fmaf(v, v, slr);
    }
    g_Prs[b * L + y * WW + x] = srs;
    g_Plr[b * L + y * WW + x] = slr;
}

// ---------------- 2. 3x3 window norms + best-init ----------------
__global__ void k_norms() {
    int i = blockIdx.x * blockDim.x + threadIdx.x;
    if (i >= BATCH * L) return;
    int b = i / L, p = i % L, y = p / WW, x = p % WW;
    float wr = 0.f, wl = 0.f;
    #pragma unroll
    for (int dy = -1; dy <= 1; dy++) {
        int yy = y + dy;
        if ((unsigned)yy >= HH) continue;
        #pragma unroll
        for (int dx = -1; dx <= 1; dx++) {
            int xx = x + dx;
            if ((unsigned)xx >= WW) continue;
            wr += g_Prs[b * L + yy * WW + xx];
            wl += g_Plr[b * L + yy * WW + xx];
        }
    }
    g_invA[i] = 1.f / fmaxf(sqrtf(wr), 1e-12f);
    g_invB[i] = 1.f / fmaxf(sqrtf(wl), 1e-12f);
    g_best[i] = 0ull;  // key 0 < any real float key
}

// ---------------- 3. Gram GEMM: G[l][m] = sum_c refsr[c][l] * lrsr[c][m] ----------------
// Both operands are already K-major [C][L]; 128x128 tile, K-chunk 8, 8x8 micro-tile.
__global__ void __launch_bounds__(256) k_gemmG(const float* __restrict__ refsr,
                                               const float* __restrict__ lrsr) {
    int b = blockIdx.z;
    int lbase = blockIdx.y * 128;
    int mbase = blockIdx.x * 128;
    const float* A = refsr + (size_t)b * C3 * L;   // [k][l]
    const float* Bm = lrsr + (size_t)b * C3 * L;   // [k][m]

    __shared__ float As[8][128];
    __shared__ float Bs[8][128];

    int t = threadIdx.x;
    int tx = t & 15, ty = t >> 4;

    float acc[8][8];
    #pragma unroll
    for (int i = 0; i < 8; i++)
        #pragma unroll
        for (int j = 0; j < 8; j++) acc[i][j] = 0.f;

    int kr = t >> 5;              // k row in chunk (0..7)
    int co = (t & 31) << 2;       // col offset (0..124)
    const float* aptr = A + (size_t)kr * L + lbase + co;
    const float* bptr = Bm + (size_t)kr * L + mbase + co;

    for (int k0 = 0; k0 < C3; k0 += 8) {
        float4 av = *(const float4*)(aptr + (size_t)k0 * L);
        float4 bv = *(const float4*)(bptr + (size_t)k0 * L);
        __syncthreads();
        *(float4*)&As[kr][co] = av;
        *(float4*)&Bs[kr][co] = bv;
        __syncthreads();
        #pragma unroll
        for (int k = 0; k < 8; k++) {
            float a[8], bb[8];
            *(float4*)&a[0] = *(const float4*)&As[k][ty * 8];
            *(float4*)&a[4] = *(const float4*)&As[k][ty * 8 + 4];
            *(float4*)&bb[0] = *(const float4*)&Bs[k][tx * 8];
            *(float4*)&bb[4] = *(const float4*)&Bs[k][tx * 8 + 4];
            #pragma unroll
            for (int i = 0; i < 8; i++)
                #pragma unroll
                for (int j = 0; j < 8; j++)
                    acc[i][j] = fmaf(a[i], bb[j], acc[i][j]);
        }
    }

    float* gout = g_G + (size_t)b * L * L;
    #pragma unroll
    for (int i = 0; i < 8; i++) {
        size_t row = (size_t)(lbase + ty * 8 + i) * L + mbase + tx * 8;
        *(float4*)&gout[row] = make_float4(acc[i][0], acc[i][1], acc[i][2], acc[i][3]);
        *(float4*)&gout[row + 4] = make_float4(acc[i][4], acc[i][5], acc[i][6], acc[i][7]);
    }
}

// ---------------- 4. diagonal 3x3 box filter of G + scaling + column argmax ----------------
// R[l,m] = invA[l]*invB[m] * sum_{o in 3x3, valid(l,o)&&valid(m,o)} G[l+d, m+d], d=48*dy+dx
// grid: (9 m-blocks of 256, 18 l-chunks of 128, BATCH); packed atomicMax reduce
#define LCHUNK 128
__global__ void __launch_bounds__(256) k_boxargmax() {
    int b = blockIdx.z;
    int m = blockIdx.x * 256 + threadIdx.x;
    int l0 = blockIdx.y * LCHUNK;
    int my = m / WW, mx = m % WW;

    __shared__ float sInvA[LCHUNK];
    __shared__ unsigned sLmask[LCHUNK];
    int t = threadIdx.x;
    if (t < LCHUNK) {
        int l = l0 + t, ly = l / WW, lx = l % WW;
        unsigned msk = 0;
        int o = 0;
        #pragma unroll
        for (int dy = -1; dy <= 1; dy++)
            #pragma unroll
            for (int dx = -1; dx <= 1; dx++, o++)
                if ((unsigned)(ly + dy) < HH && (unsigned)(lx + dx) < WW)
                    msk |= 1u << o;
        sLmask[t] = msk;
        sInvA[t] = g_invA[b * L + l];
    }
    __syncthreads();

    unsigned mmask = 0;
    {
        int o = 0;
        #pragma unroll
        for (int dy = -1; dy <= 1; dy++)
            #pragma unroll
            for (int dx = -1; dx <= 1; dx++, o++)
                if ((unsigned)(my + dy) < HH && (unsigned)(mx + dx) < WW)
                    mmask |= 1u << o;
    }

    const float invBm = g_invB[b * L + m];
    const float* gbase = g_G + (size_t)b * L * L + (size_t)l0 * L + m;
    const int doff[9] = {-49 * LP1, -48 * LP1, -47 * LP1, -LP1, 0,
                         LP1, 47 * LP1, 48 * LP1, 49 * LP1};

    float best = -1e30f;
    int barg = l0;
    for (int i = 0; i < LCHUNK; i++) {
        unsigned both = sLmask[i] & mmask;
        const float* p = gbase + (size_t)i * L;
        float s = 0.f;
        #pragma unroll
        for (int o = 0; o < 9; o++)
            if ((both >> o) & 1) s += __ldg(p + doff[o]);
        float v = s * sInvA[i] * invBm;
        if (v > best) { best = v; barg = l0 + i; }
    }

    unsigned long long pk = ((unsigned long long)fkey(best) << 32) |
                            (unsigned long long)(0xFFFFFFFFu - (unsigned)barg);
    atomicMax(&g_best[b * L + m], pk);
}

// ---------------- 5. decode best -> S output + arg indices ----------------
__global__ void k_decode(float* __restrict__ outS) {
    int i = blockIdx.x * blockDim.x + threadIdx.x;
    if (i >= BATCH * L) return;
    unsigned long long p = g_best[i];
    outS[i] = fkeyinv((unsigned)(p >> 32));
    g_arg[i] = (int)(0xFFFFFFFFu - (unsigned)(p & 0xFFFFFFFFu));
}

// ---------------- 6. gather + fold (closed form: 9 contributions/pixel) ----------------
__global__ void k_gather(const float* __restrict__ ref, float* __restrict__ out,
                         int C, int s, int Hs) {
    int b = blockIdx.z, c = blockIdx.y;
    int p = blockIdx.x * blockDim.x + threadIdx.x;
    int y = p / Hs, x = p % Hs;
    int qy = y / s, ry = y % s, qx = x / s, rxr = x % s;
    const int* argb = g_arg + b * L;
    const float* refc = ref + ((size_t)b * C + c) * Hs * Hs;
    float sum = 0.f;
    #pragma unroll
    for (int dy = 0; dy < 3; dy++) {
        int oh = qy + 1 - dy;
        if ((unsigned)oh >= HH) continue;
        int ki = ry + s * dy;
        #pragma unroll
        for (int dx = 0; dx < 3; dx++) {
            int ow = qx + 1 - dx;
            if ((unsigned)ow >= WW) continue;
            int kj = rxr + s * dx;
            int j = __ldg(argb + oh * WW + ow);
            int sy = s * (j / WW) + ki - s;
            int sx = s * (j % WW) + kj - s;
            if ((unsigned)sy < (unsigned)Hs && (unsigned)sx < (unsigned)Hs)
                sum += __ldg(refc + sy * Hs + sx);
        }
    }
    out[((size_t)b * C + c) * (size_t)(Hs * Hs) + p] = sum * (1.f / 9.f);
}

// ---------------- launch ----------------
extern "C" void kernel_launch(void* const* d_in, const int* in_sizes, int n_in,
                              void* d_out, int out_size) {
    const float* lrsr = (const float*)d_in[0];
    const float* refsr = (const float*)d_in[1];
    const float* ref1 = (const float*)d_in[2];
    const float* ref2 = (const float*)d_in[3];
    const float* ref3 = (const float*)d_in[4];
    float* out = (float*)d_out;

    float* outS = out;                            // (4,1,48,48)
    float* outT3 = outS + BATCH * L;              // (4,256,48,48)
    float* outT2 = outT3 + BATCH * C3 * HH * WW;  // (4,128,96,96)
    float* outT1 = outT2 + BATCH * 128 * 96 * 96; // (4,64,192,192)

    k_sqsum<<<BATCH * HH, 64>>>(lrsr, refsr);
    k_norms<<<(BATCH * L + 255) / 256, 256>>>();
    dim3 gg(18, 18, BATCH);
    k_gemmG<<<gg, 256>>>(refsr, lrsr);
    dim3 gb(9, 18, BATCH);
    k_boxargmax<<<gb, 256>>>();
    k_decode<<<(BATCH * L + 255) / 256, 256>>>(outS);
    k_gather<<<dim3(2304 / 256, C3, BATCH), 256>>>(ref3, outT3, C3, 1, 48);
    k_gather<<<dim3(9216 / 256, 128, BATCH), 256>>>(ref2, outT2, 128, 2, 96);
    k_gather<<<dim3(36864 / 256, 64, BATCH), 256>>>(ref1, outT1, 64, 4, 192);
}